// round 1
// baseline (speedup 1.0000x reference)
#include <cuda_runtime.h>
#include <cuda_bf16.h>
#include <math.h>

#define NN 50000
#define EE 800000
#define D  128

// ---------------- scratch (static device globals; alloc-free) ----------------
__device__ float g_q[NN * D];
__device__ float g_k[NN * D];
__device__ float g_v[NN * D];
__device__ float g_h[NN * D];
__device__ float g_logits[EE * 4];
__device__ float g_m[NN * 4];
__device__ float g_s[NN * 4];
__device__ int   g_src[EE];
__device__ int   g_dst[EE];
__device__ int   g_is64;

// ---------------- helpers ----------------
__device__ __forceinline__ void atomicMaxFloat(float* addr, float val) {
    // signbit-split trick: int-max for non-negative, uint-min for negative.
    if ((__float_as_uint(val) >> 31) == 0)
        atomicMax((int*)addr, __float_as_int(val));
    else
        atomicMin((unsigned int*)addr, __float_as_uint(val));
}

// ---------------- edge-index dtype sniff + convert ----------------
__global__ void detect_kernel(const void* ei) {
    // If the buffer is int64 (values < 2^31), every odd 32-bit word is 0.
    const int* w = (const int*)ei;
    __shared__ int nz;
    if (threadIdx.x == 0) nz = 0;
    __syncthreads();
    if (w[2 * threadIdx.x + 1] != 0) atomicOr(&nz, 1);
    __syncthreads();
    if (threadIdx.x == 0) g_is64 = (nz == 0) ? 1 : 0;
}

__global__ void convert_edges(const void* ei, int E_) {
    int e = blockIdx.x * blockDim.x + threadIdx.x;
    if (e >= E_) return;
    if (g_is64) {
        const long long* p = (const long long*)ei;
        g_src[e] = (int)p[e];
        g_dst[e] = (int)p[(size_t)E_ + e];
    } else {
        const int* p = (const int*)ei;
        g_src[e] = p[e];
        g_dst[e] = p[(size_t)E_ + e];
    }
}

// ---------------- init m = -inf, s = 0 ----------------
__global__ void init_ms(float* m, float* s, int n) {
    int t = blockIdx.x * blockDim.x + threadIdx.x;
    if (t < n) {
        m[t] = __int_as_float(0xff800000);  // -inf
        s[t] = 0.0f;
    }
}

// ---------------- GEMM: C[r, n] = sum_i X[r,i] * W[i,n] + b[n]  (K = 128) ----
__global__ __launch_bounds__(256) void gemm_bias(
    const float* __restrict__ X, const float* __restrict__ W,
    const float* __restrict__ bias, float* __restrict__ C, int nrows)
{
    const int BM = 64, BN = 64, BK = 16;
    __shared__ float As[BK][BM + 1];   // [k][m], padded to kill STS conflicts
    __shared__ float Bs[BK][BN];       // [k][n]

    int m0 = blockIdx.x * BM;
    int n0 = blockIdx.y * BN;
    int tid = threadIdx.x;
    int tx = tid & 15, ty = tid >> 4;

    float acc[4][4] = {};

    // A loader: 64 rows x 16 k, float4 along k
    int am = tid >> 2;
    int ak = (tid & 3) * 4;
    const float* Xrow = X + (size_t)(m0 + am) * D;
    bool arow_ok = (m0 + am) < nrows;
    // B loader: 16 k x 64 n, float4 along n
    int bk = tid >> 4;
    int bn = (tid & 15) * 4;

    for (int kt = 0; kt < D; kt += BK) {
        float4 av = arow_ok ? *(const float4*)(Xrow + kt + ak)
                            : make_float4(0.f, 0.f, 0.f, 0.f);
        float4 bv = *(const float4*)(W + (size_t)(kt + bk) * D + n0 + bn);
        As[ak + 0][am] = av.x;
        As[ak + 1][am] = av.y;
        As[ak + 2][am] = av.z;
        As[ak + 3][am] = av.w;
        *(float4*)&Bs[bk][bn] = bv;
        __syncthreads();
#pragma unroll
        for (int kk = 0; kk < BK; kk++) {
            float a0 = As[kk][ty * 4 + 0];
            float a1 = As[kk][ty * 4 + 1];
            float a2 = As[kk][ty * 4 + 2];
            float a3 = As[kk][ty * 4 + 3];
            float4 b4 = *(const float4*)&Bs[kk][tx * 4];
            acc[0][0] += a0 * b4.x; acc[0][1] += a0 * b4.y; acc[0][2] += a0 * b4.z; acc[0][3] += a0 * b4.w;
            acc[1][0] += a1 * b4.x; acc[1][1] += a1 * b4.y; acc[1][2] += a1 * b4.z; acc[1][3] += a1 * b4.w;
            acc[2][0] += a2 * b4.x; acc[2][1] += a2 * b4.y; acc[2][2] += a2 * b4.z; acc[2][3] += a2 * b4.w;
            acc[3][0] += a3 * b4.x; acc[3][1] += a3 * b4.y; acc[3][2] += a3 * b4.z; acc[3][3] += a3 * b4.w;
        }
        __syncthreads();
    }

    int c0 = n0 + tx * 4;
    float4 b4 = *(const float4*)(bias + c0);
#pragma unroll
    for (int i = 0; i < 4; i++) {
        int r = m0 + ty * 4 + i;
        if (r < nrows) {
            float4 o;
            o.x = acc[i][0] + b4.x;
            o.y = acc[i][1] + b4.y;
            o.z = acc[i][2] + b4.z;
            o.w = acc[i][3] + b4.w;
            *(float4*)(C + (size_t)r * D + c0) = o;
        }
    }
}

// ---------------- pass A: per-edge attention logits + atomic max -------------
template <int H>
__global__ void edge_logits_kernel(const float* __restrict__ Q,
                                   const float* __restrict__ K,
                                   float* __restrict__ logits,
                                   float* __restrict__ m, int E_)
{
    int e = blockIdx.x * (blockDim.x >> 5) + (threadIdx.x >> 5);
    if (e >= E_) return;
    int lane = threadIdx.x & 31;
    int src = g_src[e], dst = g_dst[e];
    float4 q4 = *(const float4*)(Q + (size_t)dst * D + lane * 4);
    float4 k4 = *(const float4*)(K + (size_t)src * D + lane * 4);
    float p = q4.x * k4.x + q4.y * k4.y + q4.z * k4.z + q4.w * k4.w;
    const int G = 32 / H;  // lanes per head
#pragma unroll
    for (int off = G / 2; off > 0; off >>= 1)
        p += __shfl_xor_sync(0xffffffffu, p, off);
    if ((lane & (G - 1)) == 0) {
        int h = lane / G;
        const float scale = (H == 4) ? 0.17677669529663687f   // 1/sqrt(32)
                                     : 0.08838834764831843f;  // 1/sqrt(128)
        float l = p * scale;
        logits[(size_t)e * H + h] = l;
        atomicMaxFloat(&m[dst * H + h], l);
    }
}

// ---------------- pass B: exponentiate + atomic sum --------------------------
template <int H>
__global__ void edge_exp_kernel(float* __restrict__ logits,
                                const float* __restrict__ m,
                                float* __restrict__ s, int E_)
{
    int t = blockIdx.x * blockDim.x + threadIdx.x;
    if (t >= E_ * H) return;
    int e = t / H, h = t - e * H;
    int dst = g_dst[e];
    float ex = __expf(logits[t] - m[dst * H + h]);
    logits[t] = ex;
    atomicAdd(&s[dst * H + h], ex);
}

// ---------------- pass C: weighted scatter of V ------------------------------
template <int H>
__global__ void edge_scatter_kernel(const float* __restrict__ V,
                                    const float* __restrict__ logits,
                                    const float* __restrict__ s,
                                    float* __restrict__ out, int E_)
{
    int e = blockIdx.x * (blockDim.x >> 5) + (threadIdx.x >> 5);
    if (e >= E_) return;
    int lane = threadIdx.x & 31;
    int src = g_src[e], dst = g_dst[e];
    const int G = 32 / H;
    int h = lane / G;
    float w = logits[(size_t)e * H + h] / (s[dst * H + h] + 1e-16f);
    float4 v4 = *(const float4*)(V + (size_t)src * D + lane * 4);
    float* o = out + (size_t)dst * D + lane * 4;
    atomicAdd(o + 0, v4.x * w);
    atomicAdd(o + 1, v4.y * w);
    atomicAdd(o + 2, v4.z * w);
    atomicAdd(o + 3, v4.w * w);
}

// ---------------- relu -------------------------------------------------------
__global__ void relu_kernel(float* __restrict__ p, int n4) {
    int t = blockIdx.x * blockDim.x + threadIdx.x;
    if (t >= n4) return;
    float4 v = ((float4*)p)[t];
    v.x = fmaxf(v.x, 0.f);
    v.y = fmaxf(v.y, 0.f);
    v.z = fmaxf(v.z, 0.f);
    v.w = fmaxf(v.w, 0.f);
    ((float4*)p)[t] = v;
}

// ---------------- launch -----------------------------------------------------
extern "C" void kernel_launch(void* const* d_in, const int* in_sizes, int n_in,
                              void* d_out, int out_size)
{
    const float* x    = (const float*)d_in[0];
    const void*  ei   = d_in[1];
    const float* w1q  = (const float*)d_in[2];
    const float* b1q  = (const float*)d_in[3];
    const float* w1k  = (const float*)d_in[4];
    const float* b1k  = (const float*)d_in[5];
    const float* w1v  = (const float*)d_in[6];
    const float* b1v  = (const float*)d_in[7];
    const float* w1s  = (const float*)d_in[8];
    const float* b1s  = (const float*)d_in[9];
    const float* w2q  = (const float*)d_in[10];
    const float* b2q  = (const float*)d_in[11];
    const float* w2k  = (const float*)d_in[12];
    const float* b2k  = (const float*)d_in[13];
    const float* w2v  = (const float*)d_in[14];
    const float* b2v  = (const float*)d_in[15];
    const float* w2s  = (const float*)d_in[16];
    const float* b2s  = (const float*)d_in[17];

    int N_ = in_sizes[0] / D;
    int E_ = in_sizes[1] / 2;

    float *q, *k, *v, *h, *logits, *m, *s;
    cudaGetSymbolAddress((void**)&q, g_q);
    cudaGetSymbolAddress((void**)&k, g_k);
    cudaGetSymbolAddress((void**)&v, g_v);
    cudaGetSymbolAddress((void**)&h, g_h);
    cudaGetSymbolAddress((void**)&logits, g_logits);
    cudaGetSymbolAddress((void**)&m, g_m);
    cudaGetSymbolAddress((void**)&s, g_s);

    float* out = (float*)d_out;

    detect_kernel<<<1, 128>>>(ei);
    convert_edges<<<(E_ + 255) / 256, 256>>>(ei, E_);

    dim3 gg((N_ + 63) / 64, 2);
    const int EW = 8;  // edges (warps) per 256-thread block

    // ----- layer 1 (heads=4, ch=32) -----
    init_ms<<<(N_ * 4 + 255) / 256, 256>>>(m, s, N_ * 4);
    gemm_bias<<<gg, 256>>>(x, w1q, b1q, q, N_);
    gemm_bias<<<gg, 256>>>(x, w1k, b1k, k, N_);
    gemm_bias<<<gg, 256>>>(x, w1v, b1v, v, N_);
    gemm_bias<<<gg, 256>>>(x, w1s, b1s, h, N_);   // skip connection into h
    edge_logits_kernel<4><<<(E_ + EW - 1) / EW, 256>>>(q, k, logits, m, E_);
    edge_exp_kernel<4><<<(E_ * 4 + 255) / 256, 256>>>(logits, m, s, E_);
    edge_scatter_kernel<4><<<(E_ + EW - 1) / EW, 256>>>(v, logits, s, h, E_);
    relu_kernel<<<(N_ * D / 4 + 255) / 256, 256>>>(h, N_ * D / 4);

    // ----- layer 2 (heads=1, ch=128) -----
    init_ms<<<(N_ + 255) / 256, 256>>>(m, s, N_);
    gemm_bias<<<gg, 256>>>(h, w2q, b2q, q, N_);
    gemm_bias<<<gg, 256>>>(h, w2k, b2k, k, N_);
    gemm_bias<<<gg, 256>>>(h, w2v, b2v, v, N_);
    gemm_bias<<<gg, 256>>>(h, w2s, b2s, out, N_); // skip connection into out
    edge_logits_kernel<1><<<(E_ + EW - 1) / EW, 256>>>(q, k, logits, m, E_);
    edge_exp_kernel<1><<<(E_ + 255) / 256, 256>>>(logits, m, s, E_);
    edge_scatter_kernel<1><<<(E_ + EW - 1) / EW, 256>>>(v, logits, s, out, E_);
}

// round 2
// speedup vs baseline: 1.9131x; 1.9131x over previous
#include <cuda_runtime.h>
#include <cuda_bf16.h>
#include <math.h>
#include <stdint.h>

#define NN 50000
#define EE 800000
#define D  128

// ---------------- scratch (static device globals; alloc-free) ----------------
__device__ float g_q[NN * D];
__device__ float g_k[NN * D];
__device__ float g_v[NN * D];
__device__ float g_h[NN * D];
__device__ int   g_src[EE];
__device__ int   g_dst[EE];
__device__ int   g_adj[EE];       // src ids grouped by dst
__device__ int   g_rowptr[NN + 1];
__device__ int   g_cnt[NN];
__device__ int   g_cur[NN];
__device__ int   g_is64;

// ---------------- f32x2 packed-FMA helpers ----------------
__device__ __forceinline__ void fma2(uint64_t& d, uint64_t a, uint64_t b) {
    asm("fma.rn.f32x2 %0, %1, %2, %0;" : "+l"(d) : "l"(a), "l"(b));
}
__device__ __forceinline__ uint64_t pack2(float x, float y) {
    uint64_t r;
    asm("mov.b64 %0, {%1, %2};" : "=l"(r) : "f"(x), "f"(y));
    return r;
}
__device__ __forceinline__ void unpack2(uint64_t v, float& x, float& y) {
    asm("mov.b64 {%0, %1}, %2;" : "=f"(x), "=f"(y) : "l"(v));
}

// ---------------- edge-index dtype sniff + convert ----------------
__global__ void detect_kernel(const void* ei) {
    const int* w = (const int*)ei;
    __shared__ int nz;
    if (threadIdx.x == 0) nz = 0;
    __syncthreads();
    if (w[2 * threadIdx.x + 1] != 0) atomicOr(&nz, 1);
    __syncthreads();
    if (threadIdx.x == 0) g_is64 = (nz == 0) ? 1 : 0;
}

__global__ void convert_edges(const void* ei, int E_) {
    int e = blockIdx.x * blockDim.x + threadIdx.x;
    if (e >= E_) return;
    if (g_is64) {
        const long long* p = (const long long*)ei;
        g_src[e] = (int)p[e];
        g_dst[e] = (int)p[(size_t)E_ + e];
    } else {
        const int* p = (const int*)ei;
        g_src[e] = p[e];
        g_dst[e] = p[(size_t)E_ + e];
    }
}

// ---------------- CSR build ----------------
__global__ void zero_counters(int* cnt, int* cur, int n) {
    int t = blockIdx.x * blockDim.x + threadIdx.x;
    if (t < n) { cnt[t] = 0; cur[t] = 0; }
}

__global__ void hist_kernel(int* cnt, int E_) {
    int e = blockIdx.x * blockDim.x + threadIdx.x;
    if (e < E_) atomicAdd(&cnt[g_dst[e]], 1);
}

__global__ __launch_bounds__(1024) void scan_kernel(const int* cnt, int* rowptr, int n) {
    __shared__ int part[1024];
    int tid = threadIdx.x;
    int per = (n + 1023) / 1024;
    int beg = tid * per;
    int end = min(beg + per, n);
    int s = 0;
    for (int i = beg; i < end; i++) s += cnt[i];
    part[tid] = s;
    __syncthreads();
    for (int off = 1; off < 1024; off <<= 1) {
        int v = (tid >= off) ? part[tid - off] : 0;
        __syncthreads();
        part[tid] += v;
        __syncthreads();
    }
    int run = (tid > 0) ? part[tid - 1] : 0;
    for (int i = beg; i < end; i++) { rowptr[i] = run; run += cnt[i]; }
    if (tid == 1023) rowptr[n] = run;
}

__global__ void fill_kernel(const int* rowptr, int* cur, int* adj, int E_) {
    int e = blockIdx.x * blockDim.x + threadIdx.x;
    if (e >= E_) return;
    int d = g_dst[e];
    int slot = rowptr[d] + atomicAdd(&cur[d], 1);
    adj[slot] = g_src[e];
}

// ---------------- batched GEMM: 4 x (C = X @ W + b), f32x2 FMA ----------------
struct Batch4 {
    const float* W[4];
    const float* Bv[4];
    float*       C[4];
};

__global__ __launch_bounds__(256, 2) void gemm4(
    const float* __restrict__ X, Batch4 p, int nrows)
{
    const int BM = 128, BN = 128, BK = 16;
    __shared__ float As[BK][BM + 1];  // stride 129 (LDS.32 broadcast reads)
    __shared__ float Bs[BK][BN];      // 16B-aligned pair reads

    const float* W    = p.W[blockIdx.y];
    const float* bias = p.Bv[blockIdx.y];
    float*       C    = p.C[blockIdx.y];

    int m0 = blockIdx.x * BM;
    int tid = threadIdx.x;
    int tx = tid & 15, ty = tid >> 4;

    // A loader: row = tid>>1 (0..127), k-seg = (tid&1)*8
    int ar = tid >> 1;
    int ako = (tid & 1) * 8;
    const float* Xp = X + (size_t)(m0 + ar) * D + ako;
    bool aok = (m0 + ar) < nrows;
    // B loader: k-row = tid>>4 (0..15), col = (tid&15)*8
    int bk = tid >> 4;
    int bc = (tid & 15) * 8;
    const float* Wp = W + (size_t)bk * D + bc;

    uint64_t acc[8][4];
#pragma unroll
    for (int i = 0; i < 8; i++)
#pragma unroll
        for (int j = 0; j < 4; j++) acc[i][j] = 0ull;

    for (int kt = 0; kt < D; kt += BK) {
        float4 a0, a1;
        if (aok) {
            a0 = *(const float4*)(Xp + kt);
            a1 = *(const float4*)(Xp + kt + 4);
        } else {
            a0 = make_float4(0.f, 0.f, 0.f, 0.f);
            a1 = a0;
        }
        float4 b0 = *(const float4*)(Wp + (size_t)kt * D);
        float4 b1 = *(const float4*)(Wp + (size_t)kt * D + 4);
        As[ako + 0][ar] = a0.x; As[ako + 1][ar] = a0.y;
        As[ako + 2][ar] = a0.z; As[ako + 3][ar] = a0.w;
        As[ako + 4][ar] = a1.x; As[ako + 5][ar] = a1.y;
        As[ako + 6][ar] = a1.z; As[ako + 7][ar] = a1.w;
        *(float4*)&Bs[bk][bc]     = b0;
        *(float4*)&Bs[bk][bc + 4] = b1;
        __syncthreads();
#pragma unroll
        for (int kk = 0; kk < BK; kk++) {
            ulonglong2 bb0 = *(const ulonglong2*)&Bs[kk][tx * 8];
            ulonglong2 bb1 = *(const ulonglong2*)&Bs[kk][tx * 8 + 4];
#pragma unroll
            for (int i = 0; i < 8; i++) {
                float a = As[kk][ty * 8 + i];
                uint64_t ap = pack2(a, a);
                fma2(acc[i][0], ap, bb0.x);
                fma2(acc[i][1], ap, bb0.y);
                fma2(acc[i][2], ap, bb1.x);
                fma2(acc[i][3], ap, bb1.y);
            }
        }
        __syncthreads();
    }

    int c0 = tx * 8;
    float4 bv0 = *(const float4*)(bias + c0);
    float4 bv1 = *(const float4*)(bias + c0 + 4);
#pragma unroll
    for (int i = 0; i < 8; i++) {
        int r = m0 + ty * 8 + i;
        if (r < nrows) {
            float x0, x1, x2, x3, x4, x5, x6, x7;
            unpack2(acc[i][0], x0, x1);
            unpack2(acc[i][1], x2, x3);
            unpack2(acc[i][2], x4, x5);
            unpack2(acc[i][3], x6, x7);
            float4 o0 = make_float4(x0 + bv0.x, x1 + bv0.y, x2 + bv0.z, x3 + bv0.w);
            float4 o1 = make_float4(x4 + bv1.x, x5 + bv1.y, x6 + bv1.z, x7 + bv1.w);
            *(float4*)(C + (size_t)r * D + c0)     = o0;
            *(float4*)(C + (size_t)r * D + c0 + 4) = o1;
        }
    }
}

// ---------------- fused attention: warp per dst node, online softmax ----------
template <int H>
__global__ __launch_bounds__(256) void attn_fused(
    const float* __restrict__ Q, const float* __restrict__ K,
    const float* __restrict__ V, const int* __restrict__ rowptr,
    const int* __restrict__ adj, float* __restrict__ out, int n)
{
    int node = blockIdx.x * 8 + (threadIdx.x >> 5);
    if (node >= n) return;
    int lane = threadIdx.x & 31;
    const int G = 32 / H;  // lanes per head
    const float scale = (H == 4) ? 0.17677669529663687f   // 1/sqrt(32)
                                 : 0.08838834764831843f;  // 1/sqrt(128)

    float4 q4 = *(const float4*)(Q + (size_t)node * D + lane * 4);
    int i   = rowptr[node];
    int end = rowptr[node + 1];

    float m = __int_as_float(0xff800000);  // -inf
    float s = 0.f;
    float ax = 0.f, ay = 0.f, az = 0.f, aw = 0.f;

    float4 k4, v4;
    if (i < end) {
        int sc = adj[i];
        k4 = *(const float4*)(K + (size_t)sc * D + lane * 4);
        v4 = *(const float4*)(V + (size_t)sc * D + lane * 4);
    }
    while (i < end) {
        float4 ck = k4, cv = v4;
        if (i + 1 < end) {
            int sc = adj[i + 1];
            k4 = *(const float4*)(K + (size_t)sc * D + lane * 4);
            v4 = *(const float4*)(V + (size_t)sc * D + lane * 4);
        }
        float p = ck.x * q4.x + ck.y * q4.y + ck.z * q4.z + ck.w * q4.w;
#pragma unroll
        for (int off = G / 2; off > 0; off >>= 1)
            p += __shfl_xor_sync(0xffffffffu, p, off);
        float l = p * scale;
        float mn = fmaxf(m, l);
        float corr = __expf(m - mn);  // exp(-inf) = 0 first time
        float e = __expf(l - mn);
        s = s * corr + e;
        ax = ax * corr + e * cv.x;
        ay = ay * corr + e * cv.y;
        az = az * corr + e * cv.z;
        aw = aw * corr + e * cv.w;
        m = mn;
        ++i;
    }
    float inv = 1.f / (s + 1e-16f);
    float* o = out + (size_t)node * D + lane * 4;
    float4 cur = *(float4*)o;
    cur.x += ax * inv;
    cur.y += ay * inv;
    cur.z += az * inv;
    cur.w += aw * inv;
    *(float4*)o = cur;
}

// ---------------- relu ----------------
__global__ void relu_kernel(float* __restrict__ p, int n4) {
    int t = blockIdx.x * blockDim.x + threadIdx.x;
    if (t >= n4) return;
    float4 v = ((float4*)p)[t];
    v.x = fmaxf(v.x, 0.f);
    v.y = fmaxf(v.y, 0.f);
    v.z = fmaxf(v.z, 0.f);
    v.w = fmaxf(v.w, 0.f);
    ((float4*)p)[t] = v;
}

// ---------------- launch ----------------
extern "C" void kernel_launch(void* const* d_in, const int* in_sizes, int n_in,
                              void* d_out, int out_size)
{
    const float* x   = (const float*)d_in[0];
    const void*  ei  = d_in[1];

    int N_ = in_sizes[0] / D;
    int E_ = in_sizes[1] / 2;

    float *q, *k, *v, *h;
    int *adj, *rowptr, *cnt, *cur;
    cudaGetSymbolAddress((void**)&q, g_q);
    cudaGetSymbolAddress((void**)&k, g_k);
    cudaGetSymbolAddress((void**)&v, g_v);
    cudaGetSymbolAddress((void**)&h, g_h);
    cudaGetSymbolAddress((void**)&adj, g_adj);
    cudaGetSymbolAddress((void**)&rowptr, g_rowptr);
    cudaGetSymbolAddress((void**)&cnt, g_cnt);
    cudaGetSymbolAddress((void**)&cur, g_cur);

    float* out = (float*)d_out;

    // edge prep + CSR build
    detect_kernel<<<1, 128>>>(ei);
    convert_edges<<<(E_ + 255) / 256, 256>>>(ei, E_);
    zero_counters<<<(N_ + 255) / 256, 256>>>(cnt, cur, N_);
    hist_kernel<<<(E_ + 255) / 256, 256>>>(cnt, E_);
    scan_kernel<<<1, 1024>>>(cnt, rowptr, N_);
    fill_kernel<<<(E_ + 255) / 256, 256>>>(rowptr, cur, adj, E_);

    dim3 gg((N_ + 127) / 128, 4);

    // ----- layer 1 (heads=4, ch=32) -----
    Batch4 l1;
    l1.W[0] = (const float*)d_in[2];  l1.Bv[0] = (const float*)d_in[3];  l1.C[0] = q;
    l1.W[1] = (const float*)d_in[4];  l1.Bv[1] = (const float*)d_in[5];  l1.C[1] = k;
    l1.W[2] = (const float*)d_in[6];  l1.Bv[2] = (const float*)d_in[7];  l1.C[2] = v;
    l1.W[3] = (const float*)d_in[8];  l1.Bv[3] = (const float*)d_in[9];  l1.C[3] = h;  // skip
    gemm4<<<gg, 256>>>(x, l1, N_);
    attn_fused<4><<<(N_ + 7) / 8, 256>>>(q, k, v, rowptr, adj, h, N_);
    relu_kernel<<<(N_ * D / 4 + 255) / 256, 256>>>(h, N_ * D / 4);

    // ----- layer 2 (heads=1, ch=128) -----
    Batch4 l2;
    l2.W[0] = (const float*)d_in[10]; l2.Bv[0] = (const float*)d_in[11]; l2.C[0] = q;
    l2.W[1] = (const float*)d_in[12]; l2.Bv[1] = (const float*)d_in[13]; l2.C[1] = k;
    l2.W[2] = (const float*)d_in[14]; l2.Bv[2] = (const float*)d_in[15]; l2.C[2] = v;
    l2.W[3] = (const float*)d_in[16]; l2.Bv[3] = (const float*)d_in[17]; l2.C[3] = out; // skip
    gemm4<<<gg, 256>>>(h, l2, N_);
    attn_fused<1><<<(N_ + 7) / 8, 256>>>(q, k, v, rowptr, adj, out, N_);
}

// round 5
// speedup vs baseline: 2.4909x; 1.3020x over previous
#include <cuda_runtime.h>
#include <cuda_bf16.h>
#include <math.h>
#include <stdint.h>

#define NN 50000
#define EE 800000
#define D  128

// ---------------- scratch (static device globals; alloc-free) ----------------
__device__ float g_q[NN * D];
__device__ float g_k[NN * D];
__device__ float g_v[NN * D];
__device__ float g_h[NN * D];
__device__ __nv_bfloat16 g_xhi[NN * D];
__device__ __nv_bfloat16 g_xlo[NN * D];
__device__ __nv_bfloat16 g_hhi[NN * D];
__device__ __nv_bfloat16 g_hlo[NN * D];
__device__ __nv_bfloat16 g_wh[8 * D * D];   // transposed: [b][n][k]
__device__ __nv_bfloat16 g_wl[8 * D * D];
__device__ int   g_src[EE];
__device__ int   g_dst[EE];
__device__ int   g_adj[EE];
__device__ int   g_rowptr[NN + 1];
__device__ int   g_cnt[NN];
__device__ int   g_is64;

// ---------------- warp-MMA helpers (baseline PTX, works on sm_103) -----------
__device__ __forceinline__ uint32_t smem_u32(const void* p) {
    uint32_t a;
    asm("{ .reg .u64 t; cvta.to.shared.u64 t, %1; cvt.u32.u64 %0, t; }" : "=r"(a) : "l"(p));
    return a;
}
__device__ __forceinline__ void ldmx4(uint32_t* r, uint32_t addr) {
    asm volatile("ldmatrix.sync.aligned.m8n8.x4.shared.b16 {%0,%1,%2,%3}, [%4];"
                 : "=r"(r[0]), "=r"(r[1]), "=r"(r[2]), "=r"(r[3]) : "r"(addr));
}
__device__ __forceinline__ void mma_bf16(float* d, const uint32_t* a,
                                         uint32_t b0, uint32_t b1) {
    asm volatile("mma.sync.aligned.m16n8k16.row.col.f32.bf16.bf16.f32 "
                 "{%0,%1,%2,%3}, {%4,%5,%6,%7}, {%8,%9}, {%0,%1,%2,%3};"
                 : "+f"(d[0]), "+f"(d[1]), "+f"(d[2]), "+f"(d[3])
                 : "r"(a[0]), "r"(a[1]), "r"(a[2]), "r"(a[3]), "r"(b0), "r"(b1));
}

// ---------------- edge-index dtype sniff ----------------
__global__ void detect_kernel(const void* ei) {
    const int* w = (const int*)ei;
    __shared__ int nz;
    if (threadIdx.x == 0) nz = 0;
    __syncthreads();
    if (w[2 * threadIdx.x + 1] != 0) atomicOr(&nz, 1);
    __syncthreads();
    if (threadIdx.x == 0) g_is64 = (nz == 0) ? 1 : 0;
}

// convert + histogram in one pass
__global__ void convert_hist(const void* ei, int E_) {
    int e = blockIdx.x * blockDim.x + threadIdx.x;
    if (e >= E_) return;
    int s, d;
    if (g_is64) {
        const long long* p = (const long long*)ei;
        s = (int)p[e];
        d = (int)p[(size_t)E_ + e];
    } else {
        const int* p = (const int*)ei;
        s = p[e];
        d = p[(size_t)E_ + e];
    }
    g_src[e] = s;
    g_dst[e] = d;
    atomicAdd(&g_cnt[d], 1);
}

__global__ __launch_bounds__(1024) void scan_kernel(const int* cnt, int* rowptr, int n) {
    __shared__ int part[1024];
    int tid = threadIdx.x;
    int per = (n + 1023) / 1024;
    int beg = tid * per;
    int end = min(beg + per, n);
    int s = 0;
    for (int i = beg; i < end; i++) s += cnt[i];
    part[tid] = s;
    __syncthreads();
    for (int off = 1; off < 1024; off <<= 1) {
        int v = (tid >= off) ? part[tid - off] : 0;
        __syncthreads();
        part[tid] += v;
        __syncthreads();
    }
    int run = (tid > 0) ? part[tid - 1] : 0;
    for (int i = beg; i < end; i++) { rowptr[i] = run; run += cnt[i]; }
    if (tid == 1023) rowptr[n] = run;
}

// fill CSR; consumes cnt (decrements back to 0)
__global__ void fill_kernel(const int* rowptr, int* cnt, int* adj, int E_) {
    int e = blockIdx.x * blockDim.x + threadIdx.x;
    if (e >= E_) return;
    int d = g_dst[e];
    int slot = rowptr[d] + atomicSub(&cnt[d], 1) - 1;
    adj[slot] = g_src[e];
}

// ---------------- fp32 -> bf16 hi/lo split ----------------
__global__ void xconv_kernel(const float* __restrict__ x,
                             __nv_bfloat16* __restrict__ hi,
                             __nv_bfloat16* __restrict__ lo, int n) {
    int t = blockIdx.x * blockDim.x + threadIdx.x;
    if (t >= n) return;
    float v = x[t];
    __nv_bfloat16 h = __float2bfloat16(v);
    hi[t] = h;
    lo[t] = __float2bfloat16(v - __bfloat162float(h));
}

// weights: transpose + split.  out layout [b][n][k]
struct W8 { const float* w[8]; };
__global__ void wconv_kernel(W8 p, __nv_bfloat16* __restrict__ hi,
                             __nv_bfloat16* __restrict__ lo) {
    int b = blockIdx.y;
    int t = blockIdx.x * 256 + threadIdx.x;  // 0..16383
    int n = t >> 7, k = t & 127;
    float v = p.w[b][k * D + n];
    __nv_bfloat16 h = __float2bfloat16(v);
    int o = b * D * D + t;
    hi[o] = h;
    lo[o] = __float2bfloat16(v - __bfloat162float(h));
}

// ---------------- GEMM via mma.sync bf16 (3-term split) ----------------------
// C[128 x 128] tile = A[128 x 128] @ W^T, A row-major [m][k], W stored [n][k].
// smem rows: 256 B data + 16 B pad = 272 B stride (conflict-free ldmatrix).
#define SROWB 272
#define TILE_B (128 * SROWB)            // 34816 bytes per tile
#define GEMM_SMEM (4 * TILE_B)          // Ahi, Alo, Bhi, Blo = 139264

struct GemmOut { const float* bias[4]; float* C[4]; };

__global__ __launch_bounds__(256, 1) void gemm_mma(
    const __nv_bfloat16* __restrict__ Ahi, const __nv_bfloat16* __restrict__ Alo,
    const __nv_bfloat16* __restrict__ Wh,  const __nv_bfloat16* __restrict__ Wl,
    GemmOut p, int nrows)
{
    extern __shared__ char smem[];
    char* sAh = smem;
    char* sAl = smem + TILE_B;
    char* sBh = smem + 2 * TILE_B;
    char* sBl = smem + 3 * TILE_B;

    int tid = threadIdx.x;
    int wid = tid >> 5;
    int lane = tid & 31;
    int m0 = blockIdx.x * 128;
    int b  = blockIdx.y;

    const __nv_bfloat16* wh = Wh + (size_t)b * D * D;
    const __nv_bfloat16* wl = Wl + (size_t)b * D * D;

    // ---- load 4 tiles: 2048 16B-chunks each (16 chunks of 16B per 256B row) --
#pragma unroll
    for (int i = 0; i < 8; i++) {
        int c = tid + i * 256;
        int row = c >> 4, ch = c & 15;
        size_t gofs = (size_t)row * D + ch * 8;
        uint32_t sofs = (uint32_t)row * SROWB + ch * 16;
        uint4 zero = make_uint4(0, 0, 0, 0);
        bool ok = (m0 + row) < nrows;
        size_t aofs = (size_t)(m0 + row) * D + ch * 8;
        *(uint4*)(sAh + sofs) = ok ? *(const uint4*)(Ahi + aofs) : zero;
        *(uint4*)(sAl + sofs) = ok ? *(const uint4*)(Alo + aofs) : zero;
        *(uint4*)(sBh + sofs) = *(const uint4*)(wh + gofs);
        *(uint4*)(sBl + sofs) = *(const uint4*)(wl + gofs);
    }
    __syncthreads();

    // ---- warp tiling: 2 (m) x 4 (n) warps; warp tile 64 x 32 ----
    int wm = wid >> 2, wn = wid & 3;
    int lrow = lane & 15;
    int lcolB = (lane >> 4) * 16;  // byte offset of k-half
    uint32_t aBase = smem_u32(sAh) + (uint32_t)(wm * 64 + lrow) * SROWB + lcolB;
    uint32_t bBase = smem_u32(sBh) + (uint32_t)(wn * 32 + lrow) * SROWB + lcolB;

    float acc[16][4];
#pragma unroll
    for (int i = 0; i < 16; i++)
#pragma unroll
        for (int j = 0; j < 4; j++) acc[i][j] = 0.f;

#pragma unroll
    for (int kc = 0; kc < 8; kc++) {
        uint32_t koff = kc * 32;
        uint32_t af[4][4];
        uint32_t bh[2][4], bl[2][4];
        // B frags (hi & lo): two n16-k16 blocks cover n = wn*32..wn*32+31
        ldmx4(bh[0], bBase + koff);
        ldmx4(bh[1], bBase + 16 * SROWB + koff);
        ldmx4(bl[0], bBase + TILE_B + koff);
        ldmx4(bl[1], bBase + TILE_B + 16 * SROWB + koff);
        // A hi frags, then hi*Bhi + hi*Blo
#pragma unroll
        for (int i = 0; i < 4; i++) ldmx4(af[i], aBase + (uint32_t)i * 16 * SROWB + koff);
#pragma unroll
        for (int i = 0; i < 4; i++) {
#pragma unroll
            for (int jj = 0; jj < 4; jj++) {
                int jp = jj >> 1, sel = jj & 1;
                mma_bf16(acc[i * 4 + jj], af[i], bh[jp][sel], bh[jp][sel + 2]);
            }
        }
#pragma unroll
        for (int i = 0; i < 4; i++) {
#pragma unroll
            for (int jj = 0; jj < 4; jj++) {
                int jp = jj >> 1, sel = jj & 1;
                mma_bf16(acc[i * 4 + jj], af[i], bl[jp][sel], bl[jp][sel + 2]);
            }
        }
        // A lo frags (reuse regs), lo*Bhi
#pragma unroll
        for (int i = 0; i < 4; i++) ldmx4(af[i], aBase + TILE_B + (uint32_t)i * 16 * SROWB + koff);
#pragma unroll
        for (int i = 0; i < 4; i++) {
#pragma unroll
            for (int jj = 0; jj < 4; jj++) {
                int jp = jj >> 1, sel = jj & 1;
                mma_bf16(acc[i * 4 + jj], af[i], bh[jp][sel], bh[jp][sel + 2]);
            }
        }
    }

    // ---- epilogue: bias add + store ----
    const float* bias = p.bias[b];
    float* C = p.C[b];
    int r_base = m0 + wm * 64 + (lane >> 2);
    int c_base = wn * 32 + (lane & 3) * 2;
#pragma unroll
    for (int i = 0; i < 4; i++) {
        int r0 = r_base + i * 16;
        int r1 = r0 + 8;
#pragma unroll
        for (int jj = 0; jj < 4; jj++) {
            int cc = c_base + jj * 8;
            float bx = bias[cc], by = bias[cc + 1];
            float* a = acc[i * 4 + jj];
            if (r0 < nrows) {
                float2 o = make_float2(a[0] + bx, a[1] + by);
                *(float2*)(C + (size_t)r0 * D + cc) = o;
            }
            if (r1 < nrows) {
                float2 o = make_float2(a[2] + bx, a[3] + by);
                *(float2*)(C + (size_t)r1 * D + cc) = o;
            }
        }
    }
}

// ---------------- fused attention: warp per dst node, online softmax ---------
// LAYER 1: out = relu(skip + attn) -> bf16 hi/lo     LAYER 2: outf = skip + attn
template <int H, int LAYER>
__global__ __launch_bounds__(256) void attn_fused(
    const float* __restrict__ Q, const float* __restrict__ K,
    const float* __restrict__ V, const int* __restrict__ rowptr,
    const int* __restrict__ adj, const float* __restrict__ skip,
    float* __restrict__ outf, __nv_bfloat16* __restrict__ ohi,
    __nv_bfloat16* __restrict__ olo, int n)
{
    int node = blockIdx.x * 8 + (threadIdx.x >> 5);
    if (node >= n) return;
    int lane = threadIdx.x & 31;
    const int G = 32 / H;
    const float scale = (H == 4) ? 0.17677669529663687f : 0.08838834764831843f;

    float4 q4 = *(const float4*)(Q + (size_t)node * D + lane * 4);
    int i   = rowptr[node];
    int end = rowptr[node + 1];

    float m = __int_as_float(0xff800000);
    float s = 0.f;
    float ax = 0.f, ay = 0.f, az = 0.f, aw = 0.f;

    float4 k0, v0, k1, v1;
    if (i < end) {
        int sc = adj[i];
        k0 = *(const float4*)(K + (size_t)sc * D + lane * 4);
        v0 = *(const float4*)(V + (size_t)sc * D + lane * 4);
    }
    if (i + 1 < end) {
        int sc = adj[i + 1];
        k1 = *(const float4*)(K + (size_t)sc * D + lane * 4);
        v1 = *(const float4*)(V + (size_t)sc * D + lane * 4);
    }
    for (; i < end; ++i) {
        float4 ck = k0, cv = v0;
        k0 = k1; v0 = v1;
        if (i + 2 < end) {
            int sc = adj[i + 2];
            k1 = *(const float4*)(K + (size_t)sc * D + lane * 4);
            v1 = *(const float4*)(V + (size_t)sc * D + lane * 4);
        }
        float pd = ck.x * q4.x + ck.y * q4.y + ck.z * q4.z + ck.w * q4.w;
#pragma unroll
        for (int off = G / 2; off > 0; off >>= 1)
            pd += __shfl_xor_sync(0xffffffffu, pd, off);
        float l = pd * scale;
        float mn = fmaxf(m, l);
        float corr = __expf(m - mn);
        float e = __expf(l - mn);
        s = s * corr + e;
        ax = ax * corr + e * cv.x;
        ay = ay * corr + e * cv.y;
        az = az * corr + e * cv.z;
        aw = aw * corr + e * cv.w;
        m = mn;
    }
    float inv = 1.f / (s + 1e-16f);
    size_t base = (size_t)node * D + lane * 4;
    float4 sk = *(const float4*)(skip + base);
    float f0 = sk.x + ax * inv;
    float f1 = sk.y + ay * inv;
    float f2 = sk.z + az * inv;
    float f3 = sk.w + aw * inv;
    if (LAYER == 1) {
        f0 = fmaxf(f0, 0.f); f1 = fmaxf(f1, 0.f);
        f2 = fmaxf(f2, 0.f); f3 = fmaxf(f3, 0.f);
        __nv_bfloat16 h0 = __float2bfloat16(f0), h1 = __float2bfloat16(f1);
        __nv_bfloat16 h2 = __float2bfloat16(f2), h3 = __float2bfloat16(f3);
        __nv_bfloat162 hi01, hi23, lo01, lo23;
        hi01.x = h0; hi01.y = h1; hi23.x = h2; hi23.y = h3;
        lo01.x = __float2bfloat16(f0 - __bfloat162float(h0));
        lo01.y = __float2bfloat16(f1 - __bfloat162float(h1));
        lo23.x = __float2bfloat16(f2 - __bfloat162float(h2));
        lo23.y = __float2bfloat16(f3 - __bfloat162float(h3));
        *(__nv_bfloat162*)(ohi + base) = hi01;
        *(__nv_bfloat162*)(ohi + base + 2) = hi23;
        *(__nv_bfloat162*)(olo + base) = lo01;
        *(__nv_bfloat162*)(olo + base + 2) = lo23;
    } else {
        *(float4*)(outf + base) = make_float4(f0, f1, f2, f3);
    }
}

// ---------------- launch ----------------
extern "C" void kernel_launch(void* const* d_in, const int* in_sizes, int n_in,
                              void* d_out, int out_size)
{
    const float* x  = (const float*)d_in[0];
    const void*  ei = d_in[1];

    int N_ = in_sizes[0] / D;
    int E_ = in_sizes[1] / 2;

    float *q, *k, *v, *h;
    __nv_bfloat16 *xhi, *xlo, *hhi, *hlo, *wh, *wl;
    int *adj, *rowptr, *cnt;
    cudaGetSymbolAddress((void**)&q, g_q);
    cudaGetSymbolAddress((void**)&k, g_k);
    cudaGetSymbolAddress((void**)&v, g_v);
    cudaGetSymbolAddress((void**)&h, g_h);
    cudaGetSymbolAddress((void**)&xhi, g_xhi);
    cudaGetSymbolAddress((void**)&xlo, g_xlo);
    cudaGetSymbolAddress((void**)&hhi, g_hhi);
    cudaGetSymbolAddress((void**)&hlo, g_hlo);
    cudaGetSymbolAddress((void**)&wh, g_wh);
    cudaGetSymbolAddress((void**)&wl, g_wl);
    cudaGetSymbolAddress((void**)&adj, g_adj);
    cudaGetSymbolAddress((void**)&rowptr, g_rowptr);
    cudaGetSymbolAddress((void**)&cnt, g_cnt);

    float* out = (float*)d_out;

    cudaFuncSetAttribute(gemm_mma, cudaFuncAttributeMaxDynamicSharedMemorySize, GEMM_SMEM);

    // ----- prep: edges + CSR + conversions -----
    detect_kernel<<<1, 128>>>(ei);
    cudaMemsetAsync(cnt, 0, N_ * sizeof(int));
    convert_hist<<<(E_ + 255) / 256, 256>>>(ei, E_);
    scan_kernel<<<1, 1024>>>(cnt, rowptr, N_);
    fill_kernel<<<(E_ + 255) / 256, 256>>>(rowptr, cnt, adj, E_);
    xconv_kernel<<<(N_ * D + 255) / 256, 256>>>(x, xhi, xlo, N_ * D);
    W8 w8;
    for (int j = 0; j < 8; j++) w8.w[j] = (const float*)d_in[2 + 2 * j];
    wconv_kernel<<<dim3(64, 8), 256>>>(w8, wh, wl);

    dim3 gg((N_ + 127) / 128, 4);

    // ----- layer 1 (heads=4, ch=32) -----
    GemmOut o1;
    o1.bias[0] = (const float*)d_in[3]; o1.C[0] = q;
    o1.bias[1] = (const float*)d_in[5]; o1.C[1] = k;
    o1.bias[2] = (const float*)d_in[7]; o1.C[2] = v;
    o1.bias[3] = (const float*)d_in[9]; o1.C[3] = h;   // skip
    gemm_mma<<<gg, 256, GEMM_SMEM>>>(xhi, xlo, wh, wl, o1, N_);
    attn_fused<4, 1><<<(N_ + 7) / 8, 256>>>(q, k, v, rowptr, adj, h, nullptr, hhi, hlo, N_);

    // ----- layer 2 (heads=1, ch=128) -----
    GemmOut o2;
    o2.bias[0] = (const float*)d_in[11]; o2.C[0] = q;
    o2.bias[1] = (const float*)d_in[13]; o2.C[1] = k;
    o2.bias[2] = (const float*)d_in[15]; o2.C[2] = v;
    o2.bias[3] = (const float*)d_in[17]; o2.C[3] = out;  // skip
    gemm_mma<<<gg, 256, GEMM_SMEM>>>(hhi, hlo, wh + 4 * D * D, wl + 4 * D * D, o2, N_);
    attn_fused<1, 2><<<(N_ + 7) / 8, 256>>>(q, k, v, rowptr, adj, out, out, nullptr, nullptr, N_);
}

// round 6
// speedup vs baseline: 2.6408x; 1.0602x over previous
#include <cuda_runtime.h>
#include <cuda_bf16.h>
#include <math.h>
#include <stdint.h>

#define NN 50000
#define EE 800000
#define D  128

// ---------------- scratch (static device globals; alloc-free) ----------------
__device__ float g_q[NN * D];
__device__ float g_k[NN * D];
__device__ float g_v[NN * D];
__device__ float g_h[NN * D];
__device__ __nv_bfloat16 g_xhi[NN * D];
__device__ __nv_bfloat16 g_xlo[NN * D];
__device__ __nv_bfloat16 g_hhi[NN * D];
__device__ __nv_bfloat16 g_hlo[NN * D];
__device__ __nv_bfloat16 g_wh[8 * D * D];   // transposed: [b][n][k]
__device__ __nv_bfloat16 g_wl[8 * D * D];
__device__ int   g_src[EE];
__device__ int   g_dst[EE];
__device__ int   g_adj[EE];
__device__ int   g_rowptr[NN + 1];
__device__ int   g_cnt[NN];
__device__ int   g_is64;

// ---------------- warp-MMA helpers (baseline PTX, works on sm_103) -----------
__device__ __forceinline__ uint32_t smem_u32(const void* p) {
    uint32_t a;
    asm("{ .reg .u64 t; cvta.to.shared.u64 t, %1; cvt.u32.u64 %0, t; }" : "=r"(a) : "l"(p));
    return a;
}
__device__ __forceinline__ void ldmx4(uint32_t* r, uint32_t addr) {
    asm volatile("ldmatrix.sync.aligned.m8n8.x4.shared.b16 {%0,%1,%2,%3}, [%4];"
                 : "=r"(r[0]), "=r"(r[1]), "=r"(r[2]), "=r"(r[3]) : "r"(addr));
}
__device__ __forceinline__ void mma_bf16(float* d, const uint32_t* a,
                                         uint32_t b0, uint32_t b1) {
    asm volatile("mma.sync.aligned.m16n8k16.row.col.f32.bf16.bf16.f32 "
                 "{%0,%1,%2,%3}, {%4,%5,%6,%7}, {%8,%9}, {%0,%1,%2,%3};"
                 : "+f"(d[0]), "+f"(d[1]), "+f"(d[2]), "+f"(d[3])
                 : "r"(a[0]), "r"(a[1]), "r"(a[2]), "r"(a[3]), "r"(b0), "r"(b1));
}

// ---------------- edge-index dtype sniff ----------------
__global__ void detect_kernel(const void* ei) {
    const int* w = (const int*)ei;
    __shared__ int nz;
    if (threadIdx.x == 0) nz = 0;
    __syncthreads();
    if (w[2 * threadIdx.x + 1] != 0) atomicOr(&nz, 1);
    __syncthreads();
    if (threadIdx.x == 0) g_is64 = (nz == 0) ? 1 : 0;
}

// convert + histogram in one pass
__global__ void convert_hist(const void* ei, int E_) {
    int e = blockIdx.x * blockDim.x + threadIdx.x;
    if (e >= E_) return;
    int s, d;
    if (g_is64) {
        const long long* p = (const long long*)ei;
        s = (int)p[e];
        d = (int)p[(size_t)E_ + e];
    } else {
        const int* p = (const int*)ei;
        s = p[e];
        d = p[(size_t)E_ + e];
    }
    g_src[e] = s;
    g_dst[e] = d;
    atomicAdd(&g_cnt[d], 1);
}

__global__ __launch_bounds__(1024) void scan_kernel(const int* cnt, int* rowptr, int n) {
    __shared__ int part[1024];
    int tid = threadIdx.x;
    int per = (n + 1023) / 1024;
    int beg = tid * per;
    int end = min(beg + per, n);
    int s = 0;
    for (int i = beg; i < end; i++) s += cnt[i];
    part[tid] = s;
    __syncthreads();
    for (int off = 1; off < 1024; off <<= 1) {
        int v = (tid >= off) ? part[tid - off] : 0;
        __syncthreads();
        part[tid] += v;
        __syncthreads();
    }
    int run = (tid > 0) ? part[tid - 1] : 0;
    for (int i = beg; i < end; i++) { rowptr[i] = run; run += cnt[i]; }
    if (tid == 1023) rowptr[n] = run;
}

// fill CSR; consumes cnt (decrements back to 0)
__global__ void fill_kernel(const int* rowptr, int* cnt, int* adj, int E_) {
    int e = blockIdx.x * blockDim.x + threadIdx.x;
    if (e >= E_) return;
    int d = g_dst[e];
    int slot = rowptr[d] + atomicSub(&cnt[d], 1) - 1;
    adj[slot] = g_src[e];
}

// ---------------- fp32 -> bf16 hi/lo split ----------------
__global__ void xconv_kernel(const float* __restrict__ x,
                             __nv_bfloat16* __restrict__ hi,
                             __nv_bfloat16* __restrict__ lo, int n) {
    int t = blockIdx.x * blockDim.x + threadIdx.x;
    if (t >= n) return;
    float v = x[t];
    __nv_bfloat16 h = __float2bfloat16(v);
    hi[t] = h;
    lo[t] = __float2bfloat16(v - __bfloat162float(h));
}

// weights: transpose + split.  out layout [b][n][k]
struct W8 { const float* w[8]; };
__global__ void wconv_kernel(W8 p, __nv_bfloat16* __restrict__ hi,
                             __nv_bfloat16* __restrict__ lo) {
    int b = blockIdx.y;
    int t = blockIdx.x * 256 + threadIdx.x;  // 0..16383
    int n = t >> 7, k = t & 127;
    float v = p.w[b][k * D + n];
    __nv_bfloat16 h = __float2bfloat16(v);
    int o = b * D * D + t;
    hi[o] = h;
    lo[o] = __float2bfloat16(v - __bfloat162float(h));
}

// ---------------- GEMM via mma.sync bf16 (3-term split) ----------------------
// C[128 x 128] tile = A[128 x 128] @ W^T, A row-major [m][k], W stored [n][k].
// smem rows: 256 B data + 16 B pad = 272 B stride (conflict-free ldmatrix).
#define SROWB 272
#define TILE_B (128 * SROWB)            // 34816 bytes per tile
#define GEMM_SMEM (4 * TILE_B)          // Ahi, Alo, Bhi, Blo = 139264

struct GemmOut { const float* bias[4]; float* C[4]; };

__global__ __launch_bounds__(256, 1) void gemm_mma(
    const __nv_bfloat16* __restrict__ Ahi, const __nv_bfloat16* __restrict__ Alo,
    const __nv_bfloat16* __restrict__ Wh,  const __nv_bfloat16* __restrict__ Wl,
    GemmOut p, int nrows)
{
    extern __shared__ char smem[];
    char* sAh = smem;
    char* sAl = smem + TILE_B;
    char* sBh = smem + 2 * TILE_B;
    char* sBl = smem + 3 * TILE_B;

    int tid = threadIdx.x;
    int wid = tid >> 5;
    int lane = tid & 31;
    int m0 = blockIdx.x * 128;
    int b  = blockIdx.y;

    const __nv_bfloat16* wh = Wh + (size_t)b * D * D;
    const __nv_bfloat16* wl = Wl + (size_t)b * D * D;

    // ---- load 4 tiles: 2048 16B-chunks each (16 chunks of 16B per 256B row) --
#pragma unroll
    for (int i = 0; i < 8; i++) {
        int c = tid + i * 256;
        int row = c >> 4, ch = c & 15;
        size_t gofs = (size_t)row * D + ch * 8;
        uint32_t sofs = (uint32_t)row * SROWB + ch * 16;
        uint4 zero = make_uint4(0, 0, 0, 0);
        bool ok = (m0 + row) < nrows;
        size_t aofs = (size_t)(m0 + row) * D + ch * 8;
        *(uint4*)(sAh + sofs) = ok ? *(const uint4*)(Ahi + aofs) : zero;
        *(uint4*)(sAl + sofs) = ok ? *(const uint4*)(Alo + aofs) : zero;
        *(uint4*)(sBh + sofs) = *(const uint4*)(wh + gofs);
        *(uint4*)(sBl + sofs) = *(const uint4*)(wl + gofs);
    }
    __syncthreads();

    // ---- warp tiling: 2 (m) x 4 (n) warps; warp tile 64 x 32 ----
    int wm = wid >> 2, wn = wid & 3;
    int lrow = lane & 15;
    int lcolB = (lane >> 4) * 16;  // byte offset of k-half
    uint32_t aBase = smem_u32(sAh) + (uint32_t)(wm * 64 + lrow) * SROWB + lcolB;
    uint32_t bBase = smem_u32(sBh) + (uint32_t)(wn * 32 + lrow) * SROWB + lcolB;

    float acc[16][4];
#pragma unroll
    for (int i = 0; i < 16; i++)
#pragma unroll
        for (int j = 0; j < 4; j++) acc[i][j] = 0.f;

#pragma unroll
    for (int kc = 0; kc < 8; kc++) {
        uint32_t koff = kc * 32;
        uint32_t af[4][4];
        uint32_t bh[2][4], bl[2][4];
        // B frags (hi & lo): two n16-k16 blocks cover n = wn*32..wn*32+31
        ldmx4(bh[0], bBase + koff);
        ldmx4(bh[1], bBase + 16 * SROWB + koff);
        ldmx4(bl[0], bBase + TILE_B + koff);
        ldmx4(bl[1], bBase + TILE_B + 16 * SROWB + koff);
        // A hi frags, then hi*Bhi + hi*Blo
#pragma unroll
        for (int i = 0; i < 4; i++) ldmx4(af[i], aBase + (uint32_t)i * 16 * SROWB + koff);
#pragma unroll
        for (int i = 0; i < 4; i++) {
#pragma unroll
            for (int jj = 0; jj < 4; jj++) {
                int jp = jj >> 1, sel = jj & 1;
                mma_bf16(acc[i * 4 + jj], af[i], bh[jp][sel], bh[jp][sel + 2]);
            }
        }
#pragma unroll
        for (int i = 0; i < 4; i++) {
#pragma unroll
            for (int jj = 0; jj < 4; jj++) {
                int jp = jj >> 1, sel = jj & 1;
                mma_bf16(acc[i * 4 + jj], af[i], bl[jp][sel], bl[jp][sel + 2]);
            }
        }
        // A lo frags (reuse regs), lo*Bhi
#pragma unroll
        for (int i = 0; i < 4; i++) ldmx4(af[i], aBase + TILE_B + (uint32_t)i * 16 * SROWB + koff);
#pragma unroll
        for (int i = 0; i < 4; i++) {
#pragma unroll
            for (int jj = 0; jj < 4; jj++) {
                int jp = jj >> 1, sel = jj & 1;
                mma_bf16(acc[i * 4 + jj], af[i], bh[jp][sel], bh[jp][sel + 2]);
            }
        }
    }

    // ---- epilogue: bias add + store ----
    const float* bias = p.bias[b];
    float* C = p.C[b];
    int r_base = m0 + wm * 64 + (lane >> 2);
    int c_base = wn * 32 + (lane & 3) * 2;
#pragma unroll
    for (int i = 0; i < 4; i++) {
        int r0 = r_base + i * 16;
        int r1 = r0 + 8;
#pragma unroll
        for (int jj = 0; jj < 4; jj++) {
            int cc = c_base + jj * 8;
            float bx = bias[cc], by = bias[cc + 1];
            float* a = acc[i * 4 + jj];
            if (r0 < nrows) {
                float2 o = make_float2(a[0] + bx, a[1] + by);
                *(float2*)(C + (size_t)r0 * D + cc) = o;
            }
            if (r1 < nrows) {
                float2 o = make_float2(a[2] + bx, a[3] + by);
                *(float2*)(C + (size_t)r1 * D + cc) = o;
            }
        }
    }
}

// ---------------- fused attention: warp/node, dual-edge online softmax -------
// LAYER 1: out = relu(skip + attn) -> bf16 hi/lo     LAYER 2: outf = skip + attn
template <int H, int LAYER>
__global__ __launch_bounds__(256) void attn_fused(
    const float* __restrict__ Q, const float* __restrict__ K,
    const float* __restrict__ V, const int* __restrict__ rowptr,
    const int* __restrict__ adj, const float* __restrict__ skip,
    float* __restrict__ outf, __nv_bfloat16* __restrict__ ohi,
    __nv_bfloat16* __restrict__ olo, int n)
{
    int node = blockIdx.x * 8 + (threadIdx.x >> 5);
    if (node >= n) return;
    int lane = threadIdx.x & 31;
    const int G = 32 / H;
    const float scale = (H == 4) ? 0.17677669529663687f : 0.08838834764831843f;
    const float NEGINF = __int_as_float(0xff800000);

    float4 q4 = *(const float4*)(Q + (size_t)node * D + lane * 4);
    int i   = rowptr[node];
    int end = rowptr[node + 1];

    float m = NEGINF;
    float s = 0.f;
    float ax = 0.f, ay = 0.f, az = 0.f, aw = 0.f;

    if (i < end) {
        int last = end - 1;
        size_t lofs = (size_t)lane * 4;
        // pair 0 (current) + pair 1 (prefetch)
        int e0 = i, e1 = min(i + 1, last), e2 = min(i + 2, last), e3 = min(i + 3, last);
        int sa = adj[e0], sb = adj[e1], sc2 = adj[e2], sd = adj[e3];
        float4 ka0 = *(const float4*)(K + (size_t)sa * D + lofs);
        float4 va0 = *(const float4*)(V + (size_t)sa * D + lofs);
        float4 kb0 = *(const float4*)(K + (size_t)sb * D + lofs);
        float4 vb0 = *(const float4*)(V + (size_t)sb * D + lofs);
        float4 ka1 = *(const float4*)(K + (size_t)sc2 * D + lofs);
        float4 va1 = *(const float4*)(V + (size_t)sc2 * D + lofs);
        float4 kb1 = *(const float4*)(K + (size_t)sd * D + lofs);
        float4 vb1 = *(const float4*)(V + (size_t)sd * D + lofs);

        for (; i < end; i += 2) {
            float4 cka = ka0, cva = va0, ckb = kb0, cvb = vb0;
            ka0 = ka1; va0 = va1; kb0 = kb1; vb0 = vb1;
            if (i + 4 < end) {
                int n4 = adj[i + 4], n5 = adj[min(i + 5, last)];
                ka1 = *(const float4*)(K + (size_t)n4 * D + lofs);
                va1 = *(const float4*)(V + (size_t)n4 * D + lofs);
                kb1 = *(const float4*)(K + (size_t)n5 * D + lofs);
                vb1 = *(const float4*)(V + (size_t)n5 * D + lofs);
            }
            float pa = cka.x * q4.x + cka.y * q4.y + cka.z * q4.z + cka.w * q4.w;
            float pb = ckb.x * q4.x + ckb.y * q4.y + ckb.z * q4.z + ckb.w * q4.w;
#pragma unroll
            for (int off = G / 2; off > 0; off >>= 1) {
                pa += __shfl_xor_sync(0xffffffffu, pa, off);
                pb += __shfl_xor_sync(0xffffffffu, pb, off);
            }
            float la = pa * scale;
            float lb = (i + 1 < end) ? pb * scale : NEGINF;
            float mn = fmaxf(m, fmaxf(la, lb));
            float corr = __expf(m - mn);     // exp(-inf)=0 on first iter
            float ea = __expf(la - mn);
            float eb = __expf(lb - mn);      // 0 for invalid edge
            s = s * corr + ea + eb;
            ax = ax * corr + ea * cva.x + eb * cvb.x;
            ay = ay * corr + ea * cva.y + eb * cvb.y;
            az = az * corr + ea * cva.z + eb * cvb.z;
            aw = aw * corr + ea * cva.w + eb * cvb.w;
            m = mn;
        }
    }

    float inv = 1.f / (s + 1e-16f);
    size_t base = (size_t)node * D + lane * 4;
    float4 sk = *(const float4*)(skip + base);
    float f0 = sk.x + ax * inv;
    float f1 = sk.y + ay * inv;
    float f2 = sk.z + az * inv;
    float f3 = sk.w + aw * inv;
    if (LAYER == 1) {
        f0 = fmaxf(f0, 0.f); f1 = fmaxf(f1, 0.f);
        f2 = fmaxf(f2, 0.f); f3 = fmaxf(f3, 0.f);
        __nv_bfloat16 h0 = __float2bfloat16(f0), h1 = __float2bfloat16(f1);
        __nv_bfloat16 h2 = __float2bfloat16(f2), h3 = __float2bfloat16(f3);
        __nv_bfloat162 hi01, hi23, lo01, lo23;
        hi01.x = h0; hi01.y = h1; hi23.x = h2; hi23.y = h3;
        lo01.x = __float2bfloat16(f0 - __bfloat162float(h0));
        lo01.y = __float2bfloat16(f1 - __bfloat162float(h1));
        lo23.x = __float2bfloat16(f2 - __bfloat162float(h2));
        lo23.y = __float2bfloat16(f3 - __bfloat162float(h3));
        *(__nv_bfloat162*)(ohi + base) = hi01;
        *(__nv_bfloat162*)(ohi + base + 2) = hi23;
        *(__nv_bfloat162*)(olo + base) = lo01;
        *(__nv_bfloat162*)(olo + base + 2) = lo23;
    } else {
        *(float4*)(outf + base) = make_float4(f0, f1, f2, f3);
    }
}

// ---------------- launch ----------------
extern "C" void kernel_launch(void* const* d_in, const int* in_sizes, int n_in,
                              void* d_out, int out_size)
{
    const float* x  = (const float*)d_in[0];
    const void*  ei = d_in[1];

    int N_ = in_sizes[0] / D;
    int E_ = in_sizes[1] / 2;

    float *q, *k, *v, *h;
    __nv_bfloat16 *xhi, *xlo, *hhi, *hlo, *wh, *wl;
    int *adj, *rowptr, *cnt;
    cudaGetSymbolAddress((void**)&q, g_q);
    cudaGetSymbolAddress((void**)&k, g_k);
    cudaGetSymbolAddress((void**)&v, g_v);
    cudaGetSymbolAddress((void**)&h, g_h);
    cudaGetSymbolAddress((void**)&xhi, g_xhi);
    cudaGetSymbolAddress((void**)&xlo, g_xlo);
    cudaGetSymbolAddress((void**)&hhi, g_hhi);
    cudaGetSymbolAddress((void**)&hlo, g_hlo);
    cudaGetSymbolAddress((void**)&wh, g_wh);
    cudaGetSymbolAddress((void**)&wl, g_wl);
    cudaGetSymbolAddress((void**)&adj, g_adj);
    cudaGetSymbolAddress((void**)&rowptr, g_rowptr);
    cudaGetSymbolAddress((void**)&cnt, g_cnt);

    float* out = (float*)d_out;

    cudaFuncSetAttribute(gemm_mma, cudaFuncAttributeMaxDynamicSharedMemorySize, GEMM_SMEM);

    // ----- prep: edges + CSR + conversions -----
    detect_kernel<<<1, 128>>>(ei);
    cudaMemsetAsync(cnt, 0, N_ * sizeof(int));
    convert_hist<<<(E_ + 255) / 256, 256>>>(ei, E_);
    scan_kernel<<<1, 1024>>>(cnt, rowptr, N_);
    fill_kernel<<<(E_ + 255) / 256, 256>>>(rowptr, cnt, adj, E_);
    xconv_kernel<<<(N_ * D + 255) / 256, 256>>>(x, xhi, xlo, N_ * D);
    W8 w8;
    for (int j = 0; j < 8; j++) w8.w[j] = (const float*)d_in[2 + 2 * j];
    wconv_kernel<<<dim3(64, 8), 256>>>(w8, wh, wl);

    dim3 gg((N_ + 127) / 128, 4);

    // ----- layer 1 (heads=4, ch=32) -----
    GemmOut o1;
    o1.bias[0] = (const float*)d_in[3]; o1.C[0] = q;
    o1.bias[1] = (const float*)d_in[5]; o1.C[1] = k;
    o1.bias[2] = (const float*)d_in[7]; o1.C[2] = v;
    o1.bias[3] = (const float*)d_in[9]; o1.C[3] = h;   // skip
    gemm_mma<<<gg, 256, GEMM_SMEM>>>(xhi, xlo, wh, wl, o1, N_);
    attn_fused<4, 1><<<(N_ + 7) / 8, 256>>>(q, k, v, rowptr, adj, h, nullptr, hhi, hlo, N_);

    // ----- layer 2 (heads=1, ch=128) -----
    GemmOut o2;
    o2.bias[0] = (const float*)d_in[11]; o2.C[0] = q;
    o2.bias[1] = (const float*)d_in[13]; o2.C[1] = k;
    o2.bias[2] = (const float*)d_in[15]; o2.C[2] = v;
    o2.bias[3] = (const float*)d_in[17]; o2.C[3] = out;  // skip
    gemm_mma<<<gg, 256, GEMM_SMEM>>>(hhi, hlo, wh + 4 * D * D, wl + 4 * D * D, o2, N_);
    attn_fused<1, 2><<<(N_ + 7) / 8, 256>>>(q, k, v, rowptr, adj, out, out, nullptr, nullptr, N_);
}